// round 1
// baseline (speedup 1.0000x reference)
#include <cuda_runtime.h>

#define NB 8
#define NC 256
#define NP 4096

// Scratch (device globals — no allocation allowed in kernel_launch)
__device__ float g_q[NB * NC * NP];   // [b][c][n]
__device__ float g_k[NB * NC * NP];   // [b][c][n]
__device__ float g_v[NB * NP * NC];   // [b][n][c]  (transposed for PV stage)
__device__ float g_o[NB * NC * NP];   // [b][c][n]

typedef unsigned long long ull;

__device__ __forceinline__ ull pack2(float lo, float hi) {
    ull r; asm("mov.b64 %0, {%1, %2};" : "=l"(r) : "f"(lo), "f"(hi)); return r;
}
__device__ __forceinline__ float2 unpack2(ull v) {
    float2 r; asm("mov.b64 {%0, %1}, %2;" : "=f"(r.x), "=f"(r.y) : "l"(v)); return r;
}
__device__ __forceinline__ ull fma2(ull a, ull b, ull c) {
    ull d; asm("fma.rn.f32x2 %0, %1, %2, %3;" : "=l"(d) : "l"(a), "l"(b), "l"(c)); return d;
}
__device__ __forceinline__ ull mul2(ull a, ull b) {
    ull d; asm("mul.rn.f32x2 %0, %1, %2;" : "=l"(d) : "l"(a), "l"(b)); return d;
}

// ============================================================================
// Kernel A: fused QKV projection.
// Stacked GEMM [Wq;Wk;Wv](768x256) @ x(256x4096) per batch, then mask epilogue:
//   q = mask*(Wq@x)+bq ; k = (1-mask)*(Wk@x)+bk ; v = (1-mask)*(Wv@x)+bv
// (mask is per-position scalar, so it commutes with the 1x1 conv)
// grid (64 n-tiles, 6 m-tiles of 128, 8 b), block 256 (16x16), thread 8Mx4N.
// ============================================================================
__global__ __launch_bounds__(256, 1) void qkv_kernel(
    const float* __restrict__ x, const float* __restrict__ mask,
    const float* __restrict__ Wq, const float* __restrict__ bq,
    const float* __restrict__ Wk, const float* __restrict__ bk,
    const float* __restrict__ Wv, const float* __restrict__ bv)
{
    __shared__ float Ws[32][132];   // [k][m], padded row
    __shared__ float Xs[32][64];    // [k][n]

    const int tid = threadIdx.x;
    const int tx = tid & 15;
    const int ty = tid >> 4;
    const int n0 = blockIdx.x * 64;
    const int m0 = blockIdx.y * 128;
    const int b  = blockIdx.z;

    ull acc[4][4];   // [m-pair][jj]
    #pragma unroll
    for (int mp = 0; mp < 4; mp++)
        #pragma unroll
        for (int jj = 0; jj < 4; jj++) acc[mp][jj] = 0ull;

    for (int kc = 0; kc < NC; kc += 32) {
        #pragma unroll
        for (int it = 0; it < 16; it++) {
            int idx = tid + it * 256;
            int m = idx >> 5, kk = idx & 31;
            int mg = m0 + m;
            const float* Wp = (mg < 256) ? Wq : ((mg < 512) ? Wk : Wv);
            Ws[kk][m] = Wp[(mg & 255) * 256 + kc + kk];
        }
        #pragma unroll
        for (int it = 0; it < 2; it++) {
            int idx = tid + it * 256;
            int k = idx >> 4, j4 = idx & 15;
            *reinterpret_cast<float4*>(&Xs[k][j4 * 4]) =
                *reinterpret_cast<const float4*>(&x[(size_t)(b * NC + kc + k) * NP + n0 + j4 * 4]);
        }
        __syncthreads();
        #pragma unroll 8
        for (int k = 0; k < 32; k++) {
            ulonglong2 w01 = *reinterpret_cast<const ulonglong2*>(&Ws[k][ty * 8]);
            ulonglong2 w23 = *reinterpret_cast<const ulonglong2*>(&Ws[k][ty * 8 + 4]);
            float4 xv = *reinterpret_cast<const float4*>(&Xs[k][tx * 4]);
            ull wp[4] = { w01.x, w01.y, w23.x, w23.y };
            ull xd[4] = { pack2(xv.x, xv.x), pack2(xv.y, xv.y),
                          pack2(xv.z, xv.z), pack2(xv.w, xv.w) };
            #pragma unroll
            for (int mp = 0; mp < 4; mp++)
                #pragma unroll
                for (int jj = 0; jj < 4; jj++)
                    acc[mp][jj] = fma2(wp[mp], xd[jj], acc[mp][jj]);
        }
        __syncthreads();
    }

    const int sel = m0 >> 8;   // 0:q  1:k  2:v
    float mk[4];
    #pragma unroll
    for (int jj = 0; jj < 4; jj++) mk[jj] = mask[(size_t)b * NP + n0 + tx * 4 + jj];

    #pragma unroll
    for (int mp = 0; mp < 4; mp++) {
        float2 u[4];
        #pragma unroll
        for (int jj = 0; jj < 4; jj++) u[jj] = unpack2(acc[mp][jj]);
        #pragma unroll
        for (int h = 0; h < 2; h++) {
            int o = (m0 & 255) + ty * 8 + mp * 2 + h;
            float v0 = h ? u[0].y : u[0].x;
            float v1 = h ? u[1].y : u[1].x;
            float v2 = h ? u[2].y : u[2].x;
            float v3 = h ? u[3].y : u[3].x;
            if (sel == 0) {
                float bb = bq[o];
                float4 r = make_float4(mk[0] * v0 + bb, mk[1] * v1 + bb,
                                       mk[2] * v2 + bb, mk[3] * v3 + bb);
                *reinterpret_cast<float4*>(&g_q[(size_t)(b * NC + o) * NP + n0 + tx * 4]) = r;
            } else if (sel == 1) {
                float bb = bk[o];
                float4 r = make_float4((1.f - mk[0]) * v0 + bb, (1.f - mk[1]) * v1 + bb,
                                       (1.f - mk[2]) * v2 + bb, (1.f - mk[3]) * v3 + bb);
                *reinterpret_cast<float4*>(&g_k[(size_t)(b * NC + o) * NP + n0 + tx * 4]) = r;
            } else {
                float bb = bv[o];
                // v stored [n][c]; per (n) the 8 o's of this thread are contiguous
                g_v[(size_t)(b * NP + n0 + tx * 4 + 0) * NC + o] = (1.f - mk[0]) * v0 + bb;
                g_v[(size_t)(b * NP + n0 + tx * 4 + 1) * NC + o] = (1.f - mk[1]) * v1 + bb;
                g_v[(size_t)(b * NP + n0 + tx * 4 + 2) * NC + o] = (1.f - mk[2]) * v2 + bb;
                g_v[(size_t)(b * NP + n0 + tx * 4 + 3) * NC + o] = (1.f - mk[3]) * v3 + bb;
            }
        }
    }
}

// ============================================================================
// Kernel B: flash attention, fp32, online softmax.
// grid (64 query-tiles, 8 b), block 256.
// smem: Q[256][64] resident; stream K[256][64], Vt[64][256]; P[64][64].
// Thread map: S stage (ty,tx)->rows ty*4..+3, cols tx*4..+3 (acc packed f32x2
// along rows); PV stage thread owns c in {cc*64+tx*4+d} x i in {ty*4+ii}.
// ============================================================================
__global__ __launch_bounds__(256, 1) void attn_kernel()
{
    extern __shared__ float smf[];
    float* Qs  = smf;             // 16384
    float* Ks  = smf + 16384;     // 16384
    float* Vst = smf + 32768;     // 16384 : [j][c]
    float* Ps  = smf + 49152;     // 4096  : [i][j]

    const int tid = threadIdx.x;
    const int tx = tid & 15;
    const int ty = tid >> 4;
    const int b  = blockIdx.y;
    const int i0 = blockIdx.x * 64;

    #pragma unroll
    for (int it = 0; it < 16; it++) {
        int idx = tid + it * 256;
        int c = idx >> 4, i4 = idx & 15;
        *reinterpret_cast<float4*>(&Qs[c * 64 + i4 * 4]) =
            *reinterpret_cast<const float4*>(&g_q[(size_t)(b * NC + c) * NP + i0 + i4 * 4]);
    }

    float m_i[4], l_i[4];
    #pragma unroll
    for (int ii = 0; ii < 4; ii++) { m_i[ii] = -1e30f; l_i[ii] = 0.f; }
    ulonglong2 oa[4][4];
    #pragma unroll
    for (int cc = 0; cc < 4; cc++)
        #pragma unroll
        for (int ii = 0; ii < 4; ii++) { oa[cc][ii].x = 0ull; oa[cc][ii].y = 0ull; }

    __syncthreads();

    for (int jt = 0; jt < 64; jt++) {
        const int j0 = jt * 64;
        #pragma unroll
        for (int it = 0; it < 16; it++) {
            int idx = tid + it * 256;
            int c = idx >> 4, j4 = idx & 15;
            *reinterpret_cast<float4*>(&Ks[c * 64 + j4 * 4]) =
                *reinterpret_cast<const float4*>(&g_k[(size_t)(b * NC + c) * NP + j0 + j4 * 4]);
        }
        #pragma unroll
        for (int it = 0; it < 16; it++) {
            int idx = tid + it * 256;
            int j = idx >> 6, c4 = idx & 63;
            *reinterpret_cast<float4*>(&Vst[j * 256 + c4 * 4]) =
                *reinterpret_cast<const float4*>(&g_v[(size_t)(b * NP + j0 + j) * NC + c4 * 4]);
        }
        __syncthreads();

        // ---- S = Q^T K (64x64 tile), f32x2-packed along query rows ----
        ull s2[2][4];
        #pragma unroll
        for (int ip = 0; ip < 2; ip++)
            #pragma unroll
            for (int jj = 0; jj < 4; jj++) s2[ip][jj] = 0ull;

        #pragma unroll 4
        for (int c = 0; c < NC; c++) {
            ulonglong2 q2 = *reinterpret_cast<const ulonglong2*>(&Qs[c * 64 + ty * 4]);
            float4 k4 = *reinterpret_cast<const float4*>(&Ks[c * 64 + tx * 4]);
            ull kd[4] = { pack2(k4.x, k4.x), pack2(k4.y, k4.y),
                          pack2(k4.z, k4.z), pack2(k4.w, k4.w) };
            #pragma unroll
            for (int jj = 0; jj < 4; jj++) {
                s2[0][jj] = fma2(q2.x, kd[jj], s2[0][jj]);
                s2[1][jj] = fma2(q2.y, kd[jj], s2[1][jj]);
            }
        }

        float sv[4][4];
        #pragma unroll
        for (int ip = 0; ip < 2; ip++)
            #pragma unroll
            for (int jj = 0; jj < 4; jj++) {
                float2 u = unpack2(s2[ip][jj]);
                sv[ip * 2 + 0][jj] = u.x;
                sv[ip * 2 + 1][jj] = u.y;
            }

        // ---- online softmax (rows ty*4+ii, reduce across 16 tx lanes) ----
        float al[4];
        #pragma unroll
        for (int ii = 0; ii < 4; ii++) {
            float rm = fmaxf(fmaxf(sv[ii][0], sv[ii][1]), fmaxf(sv[ii][2], sv[ii][3]));
            #pragma unroll
            for (int off = 8; off > 0; off >>= 1)
                rm = fmaxf(rm, __shfl_xor_sync(0xffffffffu, rm, off));
            float mn = fmaxf(m_i[ii], rm);
            al[ii] = __expf(m_i[ii] - mn);
            float rs = 0.f;
            #pragma unroll
            for (int jj = 0; jj < 4; jj++) {
                float p = __expf(sv[ii][jj] - mn);
                sv[ii][jj] = p;
                rs += p;
            }
            #pragma unroll
            for (int off = 8; off > 0; off >>= 1)
                rs += __shfl_xor_sync(0xffffffffu, rs, off);
            l_i[ii] = l_i[ii] * al[ii] + rs;
            m_i[ii] = mn;
            *reinterpret_cast<float4*>(&Ps[(ty * 4 + ii) * 64 + tx * 4]) =
                make_float4(sv[ii][0], sv[ii][1], sv[ii][2], sv[ii][3]);
            ull ad = pack2(al[ii], al[ii]);
            #pragma unroll
            for (int cc = 0; cc < 4; cc++) {
                oa[cc][ii].x = mul2(oa[cc][ii].x, ad);
                oa[cc][ii].y = mul2(oa[cc][ii].y, ad);
            }
        }
        __syncthreads();

        // ---- O += V @ P^T, f32x2-packed along c ----
        for (int j4 = 0; j4 < 16; j4++) {
            float4 pr[4];
            #pragma unroll
            for (int ii = 0; ii < 4; ii++)
                pr[ii] = *reinterpret_cast<const float4*>(&Ps[(ty * 4 + ii) * 64 + j4 * 4]);
            #pragma unroll
            for (int dj = 0; dj < 4; dj++) {
                int j = j4 * 4 + dj;
                ulonglong2 vv[4];
                #pragma unroll
                for (int cc = 0; cc < 4; cc++)
                    vv[cc] = *reinterpret_cast<const ulonglong2*>(&Vst[j * 256 + cc * 64 + tx * 4]);
                #pragma unroll
                for (int ii = 0; ii < 4; ii++) {
                    float p = (dj == 0) ? pr[ii].x : (dj == 1) ? pr[ii].y
                            : (dj == 2) ? pr[ii].z : pr[ii].w;
                    ull pd = pack2(p, p);
                    #pragma unroll
                    for (int cc = 0; cc < 4; cc++) {
                        oa[cc][ii].x = fma2(vv[cc].x, pd, oa[cc][ii].x);
                        oa[cc][ii].y = fma2(vv[cc].y, pd, oa[cc][ii].y);
                    }
                }
            }
        }
        __syncthreads();
    }

    float inv[4];
    #pragma unroll
    for (int ii = 0; ii < 4; ii++) inv[ii] = 1.f / l_i[ii];

    #pragma unroll
    for (int cc = 0; cc < 4; cc++) {
        float of[4][4];
        #pragma unroll
        for (int ii = 0; ii < 4; ii++) {
            float2 u0 = unpack2(oa[cc][ii].x);
            float2 u1 = unpack2(oa[cc][ii].y);
            of[ii][0] = u0.x * inv[ii];
            of[ii][1] = u0.y * inv[ii];
            of[ii][2] = u1.x * inv[ii];
            of[ii][3] = u1.y * inv[ii];
        }
        #pragma unroll
        for (int d = 0; d < 4; d++) {
            int c = cc * 64 + tx * 4 + d;
            *reinterpret_cast<float4*>(&g_o[(size_t)(b * NC + c) * NP + i0 + ty * 4]) =
                make_float4(of[0][d], of[1][d], of[2][d], of[3][d]);
        }
    }
}

// ============================================================================
// Kernel C: output projection + residual: out = Wo@O + bo + gamma*x
// grid (64 n-tiles, 2 m-tiles, 8 b)
// ============================================================================
__global__ __launch_bounds__(256, 1) void proj_kernel(
    const float* __restrict__ xin, const float* __restrict__ Wo,
    const float* __restrict__ bo, const float* __restrict__ gamma,
    float* __restrict__ out)
{
    __shared__ float Ws[32][132];
    __shared__ float Xs[32][64];

    const int tid = threadIdx.x;
    const int tx = tid & 15;
    const int ty = tid >> 4;
    const int n0 = blockIdx.x * 64;
    const int m0 = blockIdx.y * 128;
    const int b  = blockIdx.z;

    ull acc[4][4];
    #pragma unroll
    for (int mp = 0; mp < 4; mp++)
        #pragma unroll
        for (int jj = 0; jj < 4; jj++) acc[mp][jj] = 0ull;

    for (int kc = 0; kc < NC; kc += 32) {
        #pragma unroll
        for (int it = 0; it < 16; it++) {
            int idx = tid + it * 256;
            int m = idx >> 5, kk = idx & 31;
            Ws[kk][m] = Wo[(m0 + m) * 256 + kc + kk];
        }
        #pragma unroll
        for (int it = 0; it < 2; it++) {
            int idx = tid + it * 256;
            int k = idx >> 4, j4 = idx & 15;
            *reinterpret_cast<float4*>(&Xs[k][j4 * 4]) =
                *reinterpret_cast<const float4*>(&g_o[(size_t)(b * NC + kc + k) * NP + n0 + j4 * 4]);
        }
        __syncthreads();
        #pragma unroll 8
        for (int k = 0; k < 32; k++) {
            ulonglong2 w01 = *reinterpret_cast<const ulonglong2*>(&Ws[k][ty * 8]);
            ulonglong2 w23 = *reinterpret_cast<const ulonglong2*>(&Ws[k][ty * 8 + 4]);
            float4 xv = *reinterpret_cast<const float4*>(&Xs[k][tx * 4]);
            ull wp[4] = { w01.x, w01.y, w23.x, w23.y };
            ull xd[4] = { pack2(xv.x, xv.x), pack2(xv.y, xv.y),
                          pack2(xv.z, xv.z), pack2(xv.w, xv.w) };
            #pragma unroll
            for (int mp = 0; mp < 4; mp++)
                #pragma unroll
                for (int jj = 0; jj < 4; jj++)
                    acc[mp][jj] = fma2(wp[mp], xd[jj], acc[mp][jj]);
        }
        __syncthreads();
    }

    const float g0 = gamma[0];
    #pragma unroll
    for (int mp = 0; mp < 4; mp++) {
        float2 u[4];
        #pragma unroll
        for (int jj = 0; jj < 4; jj++) u[jj] = unpack2(acc[mp][jj]);
        #pragma unroll
        for (int h = 0; h < 2; h++) {
            int o = m0 + ty * 8 + mp * 2 + h;
            float bb = bo[o];
            float4 xr = *reinterpret_cast<const float4*>(&xin[(size_t)(b * NC + o) * NP + n0 + tx * 4]);
            float4 r;
            r.x = (h ? u[0].y : u[0].x) + bb + g0 * xr.x;
            r.y = (h ? u[1].y : u[1].x) + bb + g0 * xr.y;
            r.z = (h ? u[2].y : u[2].x) + bb + g0 * xr.z;
            r.w = (h ? u[3].y : u[3].x) + bb + g0 * xr.w;
            *reinterpret_cast<float4*>(&out[(size_t)(b * NC + o) * NP + n0 + tx * 4]) = r;
        }
    }
}

extern "C" void kernel_launch(void* const* d_in, const int* in_sizes, int n_in,
                              void* d_out, int out_size)
{
    const float* x     = (const float*)d_in[0];
    const float* mask  = (const float*)d_in[1];
    const float* Wq    = (const float*)d_in[2];
    const float* bq    = (const float*)d_in[3];
    const float* Wk    = (const float*)d_in[4];
    const float* bk    = (const float*)d_in[5];
    const float* Wv    = (const float*)d_in[6];
    const float* bv    = (const float*)d_in[7];
    const float* Wo    = (const float*)d_in[8];
    const float* bo    = (const float*)d_in[9];
    const float* gamma = (const float*)d_in[10];
    float* out = (float*)d_out;

    qkv_kernel<<<dim3(64, 6, NB), 256>>>(x, mask, Wq, bq, Wk, bk, Wv, bv);

    const size_t smemB = (size_t)(16384 * 3 + 4096) * sizeof(float);  // 212992 B
    cudaFuncSetAttribute(attn_kernel, cudaFuncAttributeMaxDynamicSharedMemorySize, (int)smemB);
    attn_kernel<<<dim3(64, NB), 256, smemB>>>();

    proj_kernel<<<dim3(64, 2, NB), 256>>>(x, Wo, bo, gamma, out);
}